// round 15
// baseline (speedup 1.0000x reference)
#include <cuda_runtime.h>
#include <cuda_fp16.h>
#include <cstdint>

#define KT 96
#define DD 256
#define PB 40
#define CG 8

#define MTOT 3840          // KT*PB
#define KA   512           // A split K: [Ah | Al]
#define KB   256           // B stored once (Bh); chunks reused
#define TM   128
#define TN   160
#define NCH  8             // K chunks of 64 halves
#define ROWP 72            // padded smem row stride (halves) = 144B
#define NMT  (MTOT / TM)   // 30
#define NNT  (MTOT / TN)   // 24

#define A_BUF_B (TM * ROWP * 2)   // 18432
#define B_BUF_B (TN * ROWP * 2)   // 23040
#define LUT_N   1024
#define LUT_B   (LUT_N * 8)       // float2 table, 8KB
#define SMEM_BYTES (LUT_B + 2 * (A_BUF_B + B_BUF_B))  // 91136

__device__ __align__(16) __half g_A[MTOT * KA];
__device__ __align__(16) __half g_B[MTOT * KB];
__device__ float g_pho1[KT * MTOT];   // TRANSPOSED: [l][m]
__device__ __align__(8) float2 g_lutP[LUT_N];   // (v_i, v_{i+1}) knot pairs

// ---------------------------------------------------------------------------
__device__ __forceinline__ uint32_t smem_u32(const void* p) {
    uint32_t a;
    asm("{ .reg .u64 t; cvta.to.shared.u64 t, %1; cvt.u32.u64 %0, t; }"
        : "=r"(a) : "l"(p));
    return a;
}
#define CP_ASYNC16(dst, src) \
    asm volatile("cp.async.cg.shared.global [%0], [%1], 16;" \
                 :: "r"(dst), "l"(src) : "memory")
#define CP_COMMIT() asm volatile("cp.async.commit_group;" ::: "memory")
#define CP_WAIT1()  asm volatile("cp.async.wait_group 1;" ::: "memory")
#define CP_WAIT0()  asm volatile("cp.async.wait_group 0;" ::: "memory")

#define LDSM4(r0, r1, r2, r3, a) \
    asm volatile("ldmatrix.sync.aligned.m8n8.x4.shared.b16 {%0,%1,%2,%3}, [%4];" \
                 : "=r"(r0), "=r"(r1), "=r"(r2), "=r"(r3) : "r"(a))
#define LDSM2(r0, r1, a) \
    asm volatile("ldmatrix.sync.aligned.m8n8.x2.shared.b16 {%0,%1}, [%2];" \
                 : "=r"(r0), "=r"(r1) : "r"(a))
#define MMA16816(c, a0, a1, a2, a3, b0, b1) \
    asm volatile("mma.sync.aligned.m16n8k16.row.col.f32.f16.f16.f32 " \
                 "{%0,%1,%2,%3},{%4,%5,%6,%7},{%8,%9},{%0,%1,%2,%3};" \
                 : "+f"((c)[0]), "+f"((c)[1]), "+f"((c)[2]), "+f"((c)[3]) \
                 : "r"(a0), "r"(a1), "r"(a2), "r"(a3), "r"(b0), "r"(b1))

// exact gate used only for LUT construction
__device__ __forceinline__ float gate_exact(float x, const float w1[CG],
                                            const float b1[CG], const float w2[CG]) {
    float g = 0.f;
    #pragma unroll
    for (int c = 0; c < CG; c++)
        g = fmaf(w2[c], tanhf(fmaf(x, w1[c], b1[c])), g);
    return g;
}

// LUT lookup (domain [-4,4], LUT_N intervals)
__device__ __forceinline__ float gate_lut_g(float x) {
    float t = fmaf(x, (float)(LUT_N / 8), (float)(LUT_N / 2));
    t = fminf(fmaxf(t, 0.f), (float)LUT_N - 0.001f);
    int i = (int)t;
    float f = t - (float)i;
    float2 pr = __ldg(&g_lutP[i]);
    return fmaf(f, pr.y - pr.x, pr.x);
}

// ---------------------------------------------------------------------------
// Kernel 1: single-pass prep. Thread (p, j) reads 32 column values
// (coalesced), norms reduce through smem once, then the fp16 splits are
// written straight from registers as packed uint4 stores.
// Block 192 builds the gate LUT.
// ---------------------------------------------------------------------------
__global__ __launch_bounds__(320) void prep_kernel(
    const float* __restrict__ enroll, const float* __restrict__ test,
    const float* __restrict__ fc1w, const float* __restrict__ fc1b,
    const float* __restrict__ fc2w)
{
    int b = blockIdx.x;
    int t = threadIdx.x;

    if (b == 2 * KT) {   // LUT block
        float w1[CG], b1[CG], w2[CG];
        #pragma unroll
        for (int q = 0; q < CG; q++) { w1[q] = fc1w[q]; b1[q] = fc1b[q]; w2[q] = fc2w[q]; }
        const float step = 8.0f / LUT_N;
        for (int i = t; i < LUT_N; i += 320) {
            float x0 = -4.0f + (float)i * step;
            float x1 = x0 + step;
            g_lutP[i] = make_float2(gate_exact(x0, w1, b1, w2),
                                    gate_exact(x1, w1, b1, w2));
        }
        return;
    }

    __shared__ float sred[320];
    __shared__ float scale[PB];

    bool isA = (b < KT);
    int k = isA ? b : b - KT;
    const float* in = (isA ? enroll : test) + (size_t)k * DD * PB;

    const int p = t % PB;      // column
    const int j = t / PB;      // d-group: d in [j*32, j*32+32)

    // single coalesced read pass: values stay in registers
    float v[32];
    float ss = 0.f;
    #pragma unroll
    for (int i = 0; i < 32; i++) {
        v[i] = in[(j * 32 + i) * PB + p];
        ss = fmaf(v[i], v[i], ss);
    }
    sred[t] = ss;
    __syncthreads();
    if (t < PB) {
        float ssum = 0.f;
        #pragma unroll
        for (int q = 0; q < 8; q++) ssum += sred[t + q * PB];
        scale[t] = 1.0f / fmaxf(sqrtf(ssum), 1e-12f);
    }
    __syncthreads();

    const float sc = scale[p];
    const int row = k * PB + p;

    if (isA) {
        uint4* A4 = (uint4*)g_A + (size_t)row * (KA / 8);   // 64 uint4 per row
        #pragma unroll
        for (int w = 0; w < 4; w++) {
            uint32_t hp[4], lp[4];
            #pragma unroll
            for (int e = 0; e < 4; e++) {
                float x0 = v[(w * 4 + e) * 2] * sc;
                float x1 = v[(w * 4 + e) * 2 + 1] * sc;
                __half h0 = __float2half_rn(x0), h1 = __float2half_rn(x1);
                __half l0 = __float2half_rn(x0 - __half2float(h0));
                __half l1 = __float2half_rn(x1 - __half2float(h1));
                hp[e] = ((uint32_t)__half_as_ushort(h1) << 16) | __half_as_ushort(h0);
                lp[e] = ((uint32_t)__half_as_ushort(l1) << 16) | __half_as_ushort(l0);
            }
            A4[j * 4 + w]      = make_uint4(hp[0], hp[1], hp[2], hp[3]);
            A4[32 + j * 4 + w] = make_uint4(lp[0], lp[1], lp[2], lp[3]);
        }
    } else {
        uint4* B4 = (uint4*)g_B + (size_t)row * (KB / 8);   // 32 uint4 per row
        #pragma unroll
        for (int w = 0; w < 4; w++) {
            uint32_t hp[4];
            #pragma unroll
            for (int e = 0; e < 4; e++) {
                float x0 = v[(w * 4 + e) * 2] * sc;
                float x1 = v[(w * 4 + e) * 2 + 1] * sc;
                __half h0 = __float2half_rn(x0), h1 = __float2half_rn(x1);
                hp[e] = ((uint32_t)__half_as_ushort(h1) << 16) | __half_as_ushort(h0);
            }
            B4[j * 4 + w] = make_uint4(hp[0], hp[1], hp[2], hp[3]);
        }
    }
}

// ---------------------------------------------------------------------------
// Kernel 2: mma.sync GEMM (128x160, K=512) + LUT epilogue. R11-exact.
// cb-major K order: each B chunk loaded ONCE, consumed by A-hi and A-lo.
// ---------------------------------------------------------------------------
extern __shared__ char smem_dyn[];

__device__ __forceinline__ void issue_A(int tid, uint32_t aBase,
                                        const char* gAp, int acid, int buf)
{
    #pragma unroll
    for (int it = 0; it < 4; it++) {
        int idx = tid + it * 256;
        int row = idx >> 3, seg = idx & 7;
        uint32_t dst = aBase + buf * A_BUF_B + row * (ROWP * 2) + seg * 16;
        const char* src = gAp + (size_t)row * (KA * 2) + acid * 128 + seg * 16;
        CP_ASYNC16(dst, src);
    }
}
__device__ __forceinline__ void issue_B(int tid, uint32_t bBase,
                                        const char* gBp, int bcid, int buf)
{
    #pragma unroll
    for (int it = 0; it < 5; it++) {
        int idx = tid + it * 256;
        int row = idx >> 3, seg = idx & 7;
        uint32_t dst = bBase + buf * B_BUF_B + row * (ROWP * 2) + seg * 16;
        const char* src = gBp + (size_t)row * (KB * 2) + bcid * 128 + seg * 16;
        CP_ASYNC16(dst, src);
    }
}

__global__ __launch_bounds__(256, 2) void gemm_kernel()
{
    const int tid = threadIdx.x;
    const int lane = tid & 31;
    const int wid = tid >> 5;
    const int warpM = wid >> 2;
    const int warpN = wid & 3;
    const int mt = blockIdx.x;
    const int nt = blockIdx.y;

    float2* lut = (float2*)smem_dyn;
    __half* sA = (__half*)(smem_dyn + LUT_B);
    __half* sB = (__half*)(smem_dyn + LUT_B + 2 * A_BUF_B);
    const uint32_t aBase = smem_u32(sA);
    const uint32_t bBase = smem_u32(sB);

    const char* gAp = (const char*)g_A + (size_t)mt * TM * KA * 2;
    const char* gBp = (const char*)g_B + (size_t)nt * TN * KB * 2;

    issue_A(tid, aBase, gAp, 0, 0);
    issue_B(tid, bBase, gBp, 0, 0);
    CP_COMMIT();

    for (int i = tid; i < LUT_N; i += 256)
        lut[i] = g_lutP[i];

    float acc[4][5][4];
    #pragma unroll
    for (int i = 0; i < 4; i++)
        #pragma unroll
        for (int j = 0; j < 5; j++)
            #pragma unroll
            for (int e = 0; e < 4; e++) acc[i][j][e] = 0.f;

    const int arow = lane & 15;
    const int acol = (lane & 16) ? 8 : 0;
    const uint32_t aOff0 = ((warpM * 64 + arow) * ROWP + acol) * 2;

    const int bkc = (lane & 8) ? 8 : 0;
    const int bsel = (lane & 16) ? 8 : 0;
    const uint32_t bOff0 = ((warpN * 40 + (lane & 7) + bsel) * ROWP + bkc) * 2;
    const uint32_t bOff2 = ((warpN * 40 + 32 + (lane & 7)) * ROWP + bkc) * 2;

    for (int c = 0; c < NCH; c++) {
        if (c + 1 < NCH) {
            const int cn = c + 1;
            issue_A(tid, aBase, gAp, (cn >> 1) + (cn & 1) * 4, cn & 1);
            if ((cn & 1) == 0)
                issue_B(tid, bBase, gBp, cn >> 1, (cn >> 1) & 1);
            CP_COMMIT();
            CP_WAIT1();
        } else {
            CP_WAIT0();
        }
        __syncthreads();

        const uint32_t aB = aBase + (c & 1) * A_BUF_B;
        const uint32_t bB = bBase + ((c >> 1) & 1) * B_BUF_B;
        #pragma unroll
        for (int ks = 0; ks < 4; ks++) {
            const uint32_t kadd = ks * 32;
            uint32_t af[4][4];
            #pragma unroll
            for (int mf = 0; mf < 4; mf++)
                LDSM4(af[mf][0], af[mf][1], af[mf][2], af[mf][3],
                      aB + aOff0 + mf * (16 * ROWP * 2) + kadd);
            uint32_t bw[5][2];
            LDSM4(bw[0][0], bw[0][1], bw[1][0], bw[1][1], bB + bOff0 + kadd);
            LDSM4(bw[2][0], bw[2][1], bw[3][0], bw[3][1],
                  bB + bOff0 + 16 * ROWP * 2 + kadd);
            LDSM2(bw[4][0], bw[4][1], bB + bOff2 + kadd);
            #pragma unroll
            for (int mf = 0; mf < 4; mf++)
                #pragma unroll
                for (int nf = 0; nf < 5; nf++)
                    MMA16816(acc[mf][nf], af[mf][0], af[mf][1], af[mf][2],
                             af[mf][3], bw[nf][0], bw[nf][1]);
        }
        __syncthreads();
    }

    // ---- epilogue: LUT gate, masked mean over the 40-wide l-block.
    const int g = lane >> 2;
    const int tig = lane & 3;
    const int lcol = nt * 4 + warpN;

    #pragma unroll
    for (int mf = 0; mf < 4; mf++) {
        float s0 = 0.f, c0 = 0.f, s1 = 0.f, c1 = 0.f;
        #pragma unroll
        for (int nf = 0; nf < 5; nf++) {
            #pragma unroll
            for (int e = 0; e < 4; e++) {
                float x = acc[mf][nf][e];
                float t = fmaf(x, (float)(LUT_N / 8), (float)(LUT_N / 2));
                t = fminf(fmaxf(t, 0.f), (float)LUT_N - 0.001f);
                int i = (int)t;
                float f = t - (float)i;
                float2 pr = lut[i];
                float gx = fmaf(f, pr.y - pr.x, pr.x);
                float nz = (x != 0.f) ? 1.f : 0.f;
                if (e < 2) { c0 += nz; s0 = fmaf(gx, x, s0); }
                else       { c1 += nz; s1 = fmaf(gx, x, s1); }
            }
        }
        #pragma unroll
        for (int o = 1; o <= 2; o <<= 1) {
            s0 += __shfl_xor_sync(0xffffffffu, s0, o);
            c0 += __shfl_xor_sync(0xffffffffu, c0, o);
            s1 += __shfl_xor_sync(0xffffffffu, s1, o);
            c1 += __shfl_xor_sync(0xffffffffu, c1, o);
        }
        if (tig == 0) {
            int m0 = mt * TM + warpM * 64 + mf * 16 + g;
            g_pho1[(size_t)lcol * MTOT + m0] = s0 / (c0 + 1e-6f);
            g_pho1[(size_t)lcol * MTOT + m0 + 8] = s1 / (c1 + 1e-6f);
        }
    }
}

// ---------------------------------------------------------------------------
// Kernel 3: stage-2 LUT gate + masked mean. One warp per (k,l).
// ---------------------------------------------------------------------------
__global__ __launch_bounds__(256) void stage2_kernel(float* __restrict__ out)
{
    int pair = blockIdx.x * 8 + (threadIdx.x >> 5);
    int lid = threadIdx.x & 31;
    int k = pair / KT, l = pair % KT;

    const float* row = g_pho1 + (size_t)l * MTOT + k * PB;
    float v0 = row[lid];
    float v1 = (lid < PB - 32) ? row[32 + lid] : 0.f;

    float s = 0.f, cnt = 0.f;
    cnt += (v0 != 0.0f) ? 1.0f : 0.0f;
    s = fmaf(gate_lut_g(v0), v0, s);
    if (lid < PB - 32) {
        cnt += (v1 != 0.0f) ? 1.0f : 0.0f;
        s = fmaf(gate_lut_g(v1), v1, s);
    }
    #pragma unroll
    for (int o = 16; o; o >>= 1) {
        s   += __shfl_down_sync(0xffffffffu, s, o);
        cnt += __shfl_down_sync(0xffffffffu, cnt, o);
    }
    if (lid == 0) out[k * KT + l] = s / (cnt + 1e-6f);
}

// ---------------------------------------------------------------------------
extern "C" void kernel_launch(void* const* d_in, const int* in_sizes, int n_in,
                              void* d_out, int out_size)
{
    const float* enroll = (const float*)d_in[0];
    const float* test   = (const float*)d_in[1];
    const float* fc1w   = (const float*)d_in[2];
    const float* fc1b   = (const float*)d_in[3];
    const float* fc2w   = (const float*)d_in[4];
    float* out = (float*)d_out;

    cudaFuncSetAttribute(gemm_kernel,
                         cudaFuncAttributeMaxDynamicSharedMemorySize, SMEM_BYTES);
    cudaFuncSetAttribute(gemm_kernel,
                         cudaFuncAttributePreferredSharedMemoryCarveout,
                         cudaSharedmemCarveoutMaxShared);

    prep_kernel<<<2 * KT + 1, 320>>>(enroll, test, fc1w, fc1b, fc2w);
    dim3 grid(NMT, NNT);
    gemm_kernel<<<grid, 256, SMEM_BYTES>>>();
    stage2_kernel<<<(KT * KT) / 8, 256>>>(out);
}